// round 15
// baseline (speedup 1.0000x reference)
#include <cuda_runtime.h>
#include <math.h>

// Problem dims
#define T_STEPS 1024
#define D_DIM   2048
#define NHID    2048
#define NCATS   1000

// Recurrence config (R13 core): 148 persistent blocks, 14 warps (448 thr).
// Row-pair p in [0,7): rows b*14+2p, b*14+2p+1. Warps 2p (K-half 0) and
// 2p+1 (K-half 1) co-compute the pair's 4 dots; partials combined in SMEM.
#define GBLK    148
#define WARPS   14
#define RTPB    448
#define RPB     14
#define HBUF    4          // hp ring buffers (covers pipelined anti-deps)

// ---------------- device scratch (no allocations allowed) ----------------
__device__ float    g_xz[T_STEPS * NHID];   // x @ Wz.T
__device__ float    g_xh[T_STEPS * NHID];   // x @ Wh.T
__device__ float    g_hp[HBUF][NHID];       // hp ring
__device__ float    g_logits[NCATS];
// Barrier state (R11-proven tree): 4 group counters on distinct L2 lines,
// root counter, single epoch word.
__device__ unsigned g_cnt4[128];
__device__ unsigned g_rootpad[32];
__device__ unsigned g_epochpad[32];

// ---------------- split grid barrier (pipelined) --------------------------
// arrive_ev: post this block's arrival for the event whose release value is
// `target`. Arrivals are event-ordered because every block polls the previous
// event BEFORE posting the next one, so the monotone mod-37/mod-4 counting
// (proven in R11/R13/R14) remains sound.
__device__ __forceinline__ void arrive_ev(unsigned target, int bid) {
    unsigned old = atomicAdd(&g_cnt4[(bid & 3) * 32], 1u);
    if (old % 37u == 36u) {                       // last arrival in group
        unsigned r = atomicAdd(&g_rootpad[0], 1u);
        if ((r & 3u) == 3u)                       // last group
            atomicExch(&g_epochpad[0], target);
    }
}

// poll_ev: wait until the epoch word reaches `target`. Fast path: in steady
// state the arrivals were posted one full iteration ago, so the first read
// succeeds and the nanosleep loop is never entered.
__device__ __forceinline__ void poll_ev(unsigned target) {
    if ((int)(*(volatile unsigned*)&g_epochpad[0] - target) < 0) {
        do { __nanosleep(32); }
        while ((int)(*(volatile unsigned*)&g_epochpad[0] - target) < 0);
    }
    __threadfence();
}

__device__ __forceinline__ void st_cg2(float* p, float x, float y) {
    asm volatile("st.global.cg.v2.f32 [%0], {%1,%2};" ::
                 "l"(p), "f"(x), "f"(y) : "memory");
}

// ---------------- fused input projections (unchanged, proven) ------------
#define BM 128
#define BN 128
#define BK 16

__global__ __launch_bounds__(256, 2)
void gemm_xw_kernel(const float* __restrict__ x,
                    const float* __restrict__ Wz,
                    const float* __restrict__ Wh) {
    const float* W = (blockIdx.z == 0) ? Wz : Wh;
    float* C       = (blockIdx.z == 0) ? g_xz : g_xh;

    __shared__ float As[BK][BM];
    __shared__ float Bs[BK][BN];

    const int tid = threadIdx.x;
    const int m0  = blockIdx.y * BM;
    const int n0  = blockIdx.x * BN;
    const int tr  = tid >> 4;
    const int tc  = tid & 15;

    float acc[8][8];
#pragma unroll
    for (int i = 0; i < 8; i++)
#pragma unroll
        for (int j = 0; j < 8; j++) acc[i][j] = 0.0f;

    for (int k0 = 0; k0 < D_DIM; k0 += BK) {
#pragma unroll
        for (int r = 0; r < 2; r++) {
            int idx = tid + r * 256;
            int row = idx >> 2;
            int c4  = (idx & 3) << 2;
            float4 a = *(const float4*)(x + (size_t)(m0 + row) * D_DIM + k0 + c4);
            As[c4 + 0][row] = a.x; As[c4 + 1][row] = a.y;
            As[c4 + 2][row] = a.z; As[c4 + 3][row] = a.w;
            float4 b = *(const float4*)(W + (size_t)(n0 + row) * D_DIM + k0 + c4);
            Bs[c4 + 0][row] = b.x; Bs[c4 + 1][row] = b.y;
            Bs[c4 + 2][row] = b.z; Bs[c4 + 3][row] = b.w;
        }
        __syncthreads();
#pragma unroll
        for (int kk = 0; kk < BK; kk++) {
            float ra[8], rb[8];
            *(float4*)&ra[0] = *(const float4*)&As[kk][tr * 4];
            *(float4*)&ra[4] = *(const float4*)&As[kk][64 + tr * 4];
            *(float4*)&rb[0] = *(const float4*)&Bs[kk][tc * 4];
            *(float4*)&rb[4] = *(const float4*)&Bs[kk][64 + tc * 4];
#pragma unroll
            for (int i = 0; i < 8; i++)
#pragma unroll
                for (int j = 0; j < 8; j++)
                    acc[i][j] = fmaf(ra[i], rb[j], acc[i][j]);
        }
        __syncthreads();
    }

#pragma unroll
    for (int hi = 0; hi < 2; hi++)
#pragma unroll
        for (int i = 0; i < 4; i++) {
            int row = m0 + hi * 64 + tr * 4 + i;
#pragma unroll
            for (int hj = 0; hj < 2; hj++) {
                float4 v;
                v.x = acc[hi * 4 + i][hj * 4 + 0];
                v.y = acc[hi * 4 + i][hj * 4 + 1];
                v.z = acc[hi * 4 + i][hj * 4 + 2];
                v.w = acc[hi * 4 + i][hj * 4 + 3];
                *(float4*)(C + (size_t)row * NHID + n0 + hj * 64 + tc * 4) = v;
            }
        }
}

// ---------------- persistent recurrence + classifier + softmax ------------
// SMEM U layout (float4 units): warp w gets 1024 float4 = 4 vectors x 256:
//   m=0: Uz[rp0], m=1: Uh[rp0], m=2: Uz[rp1], m=3: Uh[rp1],
//   each holding K-half q = w&1 (elements [q*1024, q*1024+1024)).
__global__ __launch_bounds__(RTPB, 1)
void recur_kernel(const float* __restrict__ Uz,
                  const float* __restrict__ Uh,
                  const float* __restrict__ bz,
                  const float* __restrict__ zt0,
                  const float* __restrict__ htilde0,
                  const float* __restrict__ hprev0,
                  const float* __restrict__ Wout,
                  float* __restrict__ out) {
    extern __shared__ float sU[];        // 14 * 4 * 1024 floats = 229376 B
    __shared__ float sred4[2][WARPS][4]; // partial-dot exchange
    __shared__ float sredW[WARPS];       // softmax scratch

    const int b   = blockIdx.x;
    const int tid = threadIdx.x;
    const int w   = tid >> 5;
    const int l   = tid & 31;
    const int p   = w >> 1;              // pair index 0..6
    const int q   = w & 1;               // K-half
    const int r0  = b * RPB + 2 * p;     // pair's first row

    // Epoch base: read before this block's first arrival (proven pattern).
    unsigned e0 = *(volatile unsigned*)&g_epochpad[0];

    // one-time: load U slices into SMEM. 56 segments of 256 float4 each.
    for (int idx = tid; idx < WARPS * 4 * 256; idx += RTPB) {
        int seg = idx >> 8;              // 0..55
        int off = idx & 255;
        int wp  = seg >> 2;              // dest warp 0..13
        int m   = seg & 3;
        int pp  = wp >> 1, qq = wp & 1;
        int r   = b * RPB + 2 * pp + (m >> 1);
        if (r < NHID) {
            const float* src = ((m & 1) ? Uh : Uz) + (size_t)r * NHID + qq * 1024;
            ((float4*)sU)[wp * 1024 + m * 256 + off] = *(const float4*)(src + off * 4);
        }
    }

    // Owner state: even warps (q==0), lanes 0/1 own rows r0, r0+1.
    int  myrow = r0 + l;
    bool owner = (q == 0) && (l < 2) && (myrow < NHID);
    float z_s = 0.f, ht_s = 0.f, h_s = 0.f, bzr = 0.f;
    if (owner) {
        z_s  = zt0[myrow];
        ht_s = htilde0[myrow];
        h_s  = hprev0[myrow];
        bzr  = bz[myrow];
    }
    // Prologue stores: hp_0 = hprev0 and hp_1 = stale combine (both known now).
    if (q == 0) {
        float h1 = (1.0f - z_s) * h_s + z_s * ht_s;     // valid on lanes 0/1
        float h0_l1 = __shfl_sync(0xffffffffu, h_s, 1);
        float h1_l1 = __shfl_sync(0xffffffffu, h1, 1);
        if (l == 0 && r0 < NHID) {
            st_cg2(&g_hp[0][r0], h_s, h0_l1);
            st_cg2(&g_hp[1][r0], h1, h1_l1);
            __threadfence();
        }
        if (owner) h_s = h1;             // h_s tracks hp_{t+1} inside the loop
    }
    __syncthreads();
    // Full barrier T_{-1}=e0+1 (covers hp_0), then post T_0=e0+2 (covers hp_1).
    if (tid == 0) {
        __threadfence();
        arrive_ev(e0 + 1, b);
        poll_ev(e0 + 1);
        arrive_ev(e0 + 2, b);
    }
    __syncthreads();

    const float4* uw = ((const float4*)sU) + (size_t)w * 1024;

    // Iterations t = 0..1022. Tail of iter t: stores hp_{t+2}, polls T_t
    // (posted by everyone one iteration earlier -> returns immediately),
    // then posts T_{t+1}. Barrier round-trip + skew hidden by 1-iter slack.
    for (int t = 0; t < T_STEPS - 1; t++) {
        // This warp's K-half of hp_t (protected by poll(T_{t-1})).
        const float4* hpg = ((const float4*)g_hp[t & 3]) + q * 256;
        float4 hp[8];
#pragma unroll
        for (int j = 0; j < 8; j++)
            hp[j] = __ldcg(hpg + l + 32 * j);

        float xzv = 0.f, xhv = 0.f;
        if (owner) {
            xzv = __ldg(&g_xz[(size_t)t * NHID + myrow]);
            xhv = __ldg(&g_xh[(size_t)t * NHID + myrow]);
        }

        // 4 partial dots over this K-half.
        float d0 = 0.f, d1 = 0.f, d2 = 0.f, d3 = 0.f;
#pragma unroll
        for (int j = 0; j < 8; j++) {
            float4 hv = hp[j];
            float4 a0 = uw[0 * 256 + l + 32 * j];
            d0 = fmaf(a0.x, hv.x, d0); d0 = fmaf(a0.y, hv.y, d0);
            d0 = fmaf(a0.z, hv.z, d0); d0 = fmaf(a0.w, hv.w, d0);
            float4 a1 = uw[1 * 256 + l + 32 * j];
            d1 = fmaf(a1.x, hv.x, d1); d1 = fmaf(a1.y, hv.y, d1);
            d1 = fmaf(a1.z, hv.z, d1); d1 = fmaf(a1.w, hv.w, d1);
            float4 a2 = uw[2 * 256 + l + 32 * j];
            d2 = fmaf(a2.x, hv.x, d2); d2 = fmaf(a2.y, hv.y, d2);
            d2 = fmaf(a2.z, hv.z, d2); d2 = fmaf(a2.w, hv.w, d2);
            float4 a3 = uw[3 * 256 + l + 32 * j];
            d3 = fmaf(a3.x, hv.x, d3); d3 = fmaf(a3.y, hv.y, d3);
            d3 = fmaf(a3.z, hv.z, d3); d3 = fmaf(a3.w, hv.w, d3);
        }
#pragma unroll
        for (int o = 16; o > 0; o >>= 1) {
            d0 += __shfl_xor_sync(0xffffffffu, d0, o);
            d1 += __shfl_xor_sync(0xffffffffu, d1, o);
            d2 += __shfl_xor_sync(0xffffffffu, d2, o);
            d3 += __shfl_xor_sync(0xffffffffu, d3, o);
        }

        if (l == 0) {
            float4 v; v.x = d0; v.y = d1; v.z = d2; v.w = d3;
            *(float4*)&sred4[t & 1][w][0] = v;
        }
        __syncthreads();                          // A: partials exchanged

        if (owner) {
            // partial order: [dz(rp0), dh(rp0), dz(rp1), dh(rp1)]
            float dz = sred4[t & 1][2 * p][2 * l + 0] + sred4[t & 1][2 * p + 1][2 * l + 0];
            float dh = sred4[t & 1][2 * p][2 * l + 1] + sred4[t & 1][2 * p + 1][2 * l + 1];
            z_s  = 1.0f / (1.0f + expf(-(xzv + dz + bzr)));
            ht_s = tanhf(xhv + dh);
            // hp_{t+2} = (1-z_t)*hp_{t+1} + z_t*ht_t  (reference order)
            h_s = (1.0f - z_s) * h_s + z_s * ht_s;
        }
        if (q == 0) {
            float hnb = __shfl_sync(0xffffffffu, h_s, 1);
            if (l == 0 && r0 < NHID) {
                st_cg2(&g_hp[(t + 2) & 3][r0], h_s, hnb);
                __threadfence();
            }
        }
        __syncthreads();                          // B: stores done block-wide
        if (tid == 0) {
            __threadfence();
            poll_ev(e0 + 2 + t);                  // T_t   (ensures hp_{t+1} ready)
            arrive_ev(e0 + 3 + t, b);             // T_{t+1} (covers hp_{t+2})
        }
        __syncthreads();                          // C
    }

    // hp_{1024} (final h) stored at end of iter 1022 into slot 0; covered by
    // T_{1023} = e0+1025 (posted at end of iter 1022 by every block).
    if (tid == 0) poll_ev(e0 + 1025);
    __syncthreads();

    // logits: warp gw = b*14 + w computes one category.
    {
        int gw = b * WARPS + w;
        if (gw < NCATS) {
            const float4* wo = (const float4*)(Wout + (size_t)gw * NHID);
            const float4* hf = (const float4*)(g_hp[0]);
            float s = 0.f;
#pragma unroll
            for (int j = 0; j < 16; j++) {
                float4 wv = __ldg(wo + l + 32 * j);
                float4 hv = __ldcg(hf + l + 32 * j);
                s = fmaf(wv.x, hv.x, s); s = fmaf(wv.y, hv.y, s);
                s = fmaf(wv.z, hv.z, s); s = fmaf(wv.w, hv.w, s);
            }
#pragma unroll
            for (int o = 16; o > 0; o >>= 1)
                s += __shfl_xor_sync(0xffffffffu, s, o);
            if (l == 0) g_logits[gw] = s;
        }
    }
    __syncthreads();
    if (tid == 0) {
        __threadfence();
        arrive_ev(e0 + 1026, b);
        poll_ev(e0 + 1026);
    }
    __syncthreads();

    // softmax over 1000 logits by block 0
    if (b == 0) {
        float m = -1e30f;
        for (int c = tid; c < NCATS; c += RTPB)
            m = fmaxf(m, __ldcg(&g_logits[c]));
#pragma unroll
        for (int o = 16; o > 0; o >>= 1)
            m = fmaxf(m, __shfl_xor_sync(0xffffffffu, m, o));
        if (l == 0) sredW[w] = m;
        __syncthreads();
        if (tid < 32) {
            float mm = (tid < WARPS) ? sredW[tid] : -1e30f;
#pragma unroll
            for (int o = 16; o > 0; o >>= 1)
                mm = fmaxf(mm, __shfl_xor_sync(0xffffffffu, mm, o));
            if (tid == 0) sredW[0] = mm;
        }
        __syncthreads();
        float gmax = sredW[0];
        __syncthreads();
        float s = 0.f;
        for (int c = tid; c < NCATS; c += RTPB)
            s += expf(__ldcg(&g_logits[c]) - gmax);
#pragma unroll
        for (int o = 16; o > 0; o >>= 1)
            s += __shfl_xor_sync(0xffffffffu, s, o);
        if (l == 0) sredW[w] = s;
        __syncthreads();
        if (tid < 32) {
            float ss = (tid < WARPS) ? sredW[tid] : 0.f;
#pragma unroll
            for (int o = 16; o > 0; o >>= 1)
                ss += __shfl_xor_sync(0xffffffffu, ss, o);
            if (tid == 0) sredW[0] = ss;
        }
        __syncthreads();
        float inv = 1.0f / sredW[0];
        for (int c = tid; c < NCATS; c += RTPB)
            out[c] = expf(__ldcg(&g_logits[c]) - gmax) * inv;
    }
}

// ---------------- launch ----------------
extern "C" void kernel_launch(void* const* d_in, const int* in_sizes, int n_in,
                              void* d_out, int out_size) {
    (void)in_sizes; (void)n_in; (void)out_size;
    const float* x    = (const float*)d_in[0];
    const float* Wh   = (const float*)d_in[1];
    const float* Wz   = (const float*)d_in[2];
    // d_in[3] = Wr : dead (rt never used)
    const float* Uh   = (const float*)d_in[4];
    const float* Uz   = (const float*)d_in[5];
    const float* bz   = (const float*)d_in[6];
    // d_in[7] = Ur, d_in[8] = br : dead
    const float* Wout = (const float*)d_in[9];
    // d_in[10] = h0 : dead (overwritten before first use)
    const float* zt0  = (const float*)d_in[11];
    const float* ht0  = (const float*)d_in[12];
    const float* hp0  = (const float*)d_in[13];
    float* out = (float*)d_out;

    const int smem = WARPS * 4 * 1024 * (int)sizeof(float);  // 229376 B
    cudaFuncSetAttribute(recur_kernel,
                         cudaFuncAttributeMaxDynamicSharedMemorySize, smem);

    dim3 ggrid(NHID / BN, T_STEPS / BM, 2);
    gemm_xw_kernel<<<ggrid, 256>>>(x, Wz, Wh);
    recur_kernel<<<GBLK, RTPB, smem>>>(Uz, Uh, bz, zt0, ht0, hp0, Wout, out);
}

// round 17
// speedup vs baseline: 1.2667x; 1.2667x over previous
#include <cuda_runtime.h>
#include <math.h>

// Problem dims
#define T_STEPS 1024
#define D_DIM   2048
#define NHID    2048
#define NCATS   1000

// Recurrence config: 148 persistent blocks, 14 compute warps + 1 sweeper
// warp (480 thr). Row-pair p in [0,7): rows b*14+2p, b*14+2p+1. Warps 2p
// (K-half 0) and 2p+1 (K-half 1) co-compute the pair's 4 dots.
#define GBLK    148
#define CWARPS  14
#define CTPB    448            // compute threads (named-barrier count)
#define RTPB    480            // total threads (incl. sweeper warp)
#define RPB     14
#define HBUF    4              // hp ring (distance-2 writes => 4 slots safe)

// ---------------- device scratch (no allocations allowed) ----------------
__device__ float    g_xz[T_STEPS * NHID];   // x @ Wz.T
__device__ float    g_xh[T_STEPS * NHID];   // x @ Wh.T
__device__ float    g_hp[HBUF][NHID];       // hp ring
__device__ float    g_logits[NCATS];
__device__ unsigned g_flags[160];           // per-block monotone progress flags
__device__ unsigned g_epochpad[32];         // epoch at [0]; SINGLE writer (sweeper)

// asm volatile L2 ops (cannot be hoisted/CSE'd out of spin loops)
__device__ __forceinline__ unsigned ld_flag(const unsigned* p) {
    unsigned v;
    asm volatile("ld.global.cg.u32 %0, [%1];" : "=r"(v) : "l"(p));
    return v;
}
__device__ __forceinline__ void st_flag(unsigned* p, unsigned v) {
    asm volatile("st.global.cg.u32 [%0], %1;" :: "l"(p), "r"(v) : "memory");
}
__device__ __forceinline__ void st_cg2(float* p, float x, float y) {
    asm volatile("st.global.cg.v2.f32 [%0], {%1,%2};" ::
                 "l"(p), "f"(x), "f"(y) : "memory");
}

// Poll the (single-writer) epoch word: proven volatile+nanosleep pattern.
__device__ __forceinline__ void poll_ev(unsigned target) {
    while ((int)(*(volatile unsigned*)&g_epochpad[0] - target) < 0) {
        __nanosleep(32);
    }
    __threadfence();
}

// Named barrier over the 448 compute threads (sweeper warp excluded).
__device__ __forceinline__ void cbar() {
    asm volatile("bar.sync 1, %0;" :: "r"(CTPB) : "memory");
}

// ---------------- fused input projections (unchanged, proven) ------------
#define BM 128
#define BN 128
#define BK 16

__global__ __launch_bounds__(256, 2)
void gemm_xw_kernel(const float* __restrict__ x,
                    const float* __restrict__ Wz,
                    const float* __restrict__ Wh) {
    const float* W = (blockIdx.z == 0) ? Wz : Wh;
    float* C       = (blockIdx.z == 0) ? g_xz : g_xh;

    __shared__ float As[BK][BM];
    __shared__ float Bs[BK][BN];

    const int tid = threadIdx.x;
    const int m0  = blockIdx.y * BM;
    const int n0  = blockIdx.x * BN;
    const int tr  = tid >> 4;
    const int tc  = tid & 15;

    float acc[8][8];
#pragma unroll
    for (int i = 0; i < 8; i++)
#pragma unroll
        for (int j = 0; j < 8; j++) acc[i][j] = 0.0f;

    for (int k0 = 0; k0 < D_DIM; k0 += BK) {
#pragma unroll
        for (int r = 0; r < 2; r++) {
            int idx = tid + r * 256;
            int row = idx >> 2;
            int c4  = (idx & 3) << 2;
            float4 a = *(const float4*)(x + (size_t)(m0 + row) * D_DIM + k0 + c4);
            As[c4 + 0][row] = a.x; As[c4 + 1][row] = a.y;
            As[c4 + 2][row] = a.z; As[c4 + 3][row] = a.w;
            float4 b = *(const float4*)(W + (size_t)(n0 + row) * D_DIM + k0 + c4);
            Bs[c4 + 0][row] = b.x; Bs[c4 + 1][row] = b.y;
            Bs[c4 + 2][row] = b.z; Bs[c4 + 3][row] = b.w;
        }
        __syncthreads();
#pragma unroll
        for (int kk = 0; kk < BK; kk++) {
            float ra[8], rb[8];
            *(float4*)&ra[0] = *(const float4*)&As[kk][tr * 4];
            *(float4*)&ra[4] = *(const float4*)&As[kk][64 + tr * 4];
            *(float4*)&rb[0] = *(const float4*)&Bs[kk][tc * 4];
            *(float4*)&rb[4] = *(const float4*)&Bs[kk][64 + tc * 4];
#pragma unroll
            for (int i = 0; i < 8; i++)
#pragma unroll
                for (int j = 0; j < 8; j++)
                    acc[i][j] = fmaf(ra[i], rb[j], acc[i][j]);
        }
        __syncthreads();
    }

#pragma unroll
    for (int hi = 0; hi < 2; hi++)
#pragma unroll
        for (int i = 0; i < 4; i++) {
            int row = m0 + hi * 64 + tr * 4 + i;
#pragma unroll
            for (int hj = 0; hj < 2; hj++) {
                float4 v;
                v.x = acc[hi * 4 + i][hj * 4 + 0];
                v.y = acc[hi * 4 + i][hj * 4 + 1];
                v.z = acc[hi * 4 + i][hj * 4 + 2];
                v.w = acc[hi * 4 + i][hj * 4 + 3];
                *(float4*)(C + (size_t)row * NHID + n0 + hj * 64 + tc * 4) = v;
            }
        }
}

// ---------------- persistent recurrence + classifier + softmax ------------
// SMEM U layout (float4 units): warp w gets 1024 float4 = 4 vectors x 256:
//   m=0: Uz[rp0], m=1: Uh[rp0], m=2: Uz[rp1], m=3: Uh[rp1],
//   each holding K-half q = w&1 (elements [q*1024, q*1024+1024)).
// Flag protocol (all monotone, base e0 = epoch at entry):
//   e0+1     : prologue stores (hp_0, hp_1) done
//   e0+t+2   : end of iter t (hp_{t+2} stored), t = 0..1022  -> max e0+1024
//   e0+1025  : logits stored
// Sweeper (block 0, warp 14) publishes epoch = min(all flags); exits at
// e0+1025. Reads of hp_t at iter t poll epoch >= e0+max(t,1) -- the flag
// written TWO iterations earlier, so the poll fast-path always hits.
__global__ __launch_bounds__(RTPB, 1)
void recur_kernel(const float* __restrict__ Uz,
                  const float* __restrict__ Uh,
                  const float* __restrict__ bz,
                  const float* __restrict__ zt0,
                  const float* __restrict__ htilde0,
                  const float* __restrict__ hprev0,
                  const float* __restrict__ Wout,
                  float* __restrict__ out) {
    extern __shared__ float sU[];          // 14 * 4 * 1024 floats = 229376 B
    __shared__ float sred4[2][CWARPS][4];  // partial-dot exchange
    __shared__ float sredW[CWARPS];        // softmax scratch

    const int b   = blockIdx.x;
    const int tid = threadIdx.x;
    const int w   = tid >> 5;
    const int l   = tid & 31;

    // ---------------- sweeper warp ----------------
    if (w == CWARPS) {
        if (b != 0) return;                // only block 0 sweeps
        // e0 read is safe: epoch has a single writer (this warp).
        unsigned e0s = *(volatile unsigned*)&g_epochpad[0];
        unsigned fin = e0s + 1025u;
        unsigned last = e0s;
        for (;;) {
            unsigned mn = 0xffffffffu;
#pragma unroll
            for (int i = 0; i < 5; i++) {
                int idx = l + i * 32;
                if (idx < GBLK) mn = min(mn, ld_flag(&g_flags[idx]));
            }
#pragma unroll
            for (int o = 16; o > 0; o >>= 1)
                mn = min(mn, __shfl_xor_sync(0xffffffffu, mn, o));
            if (l == 0 && (int)(mn - last) > 0) {
                st_flag(&g_epochpad[0], mn);
            }
            last = mn;
            if ((int)(mn - fin) >= 0) break;
        }
        return;
    }

    // ---------------- compute warps (448 threads) ----------------
    const int p  = w >> 1;                 // pair index 0..6
    const int q  = w & 1;                  // K-half
    const int r0 = b * RPB + 2 * p;        // pair's first row

    // e0: read BEFORE this block's first flag write; epoch cannot advance
    // until every block has flagged (sweeper takes a global min), so all
    // blocks observe the same base.
    unsigned e0 = *(volatile unsigned*)&g_epochpad[0];

    // one-time: load U slices into SMEM. 56 segments of 256 float4 each.
    for (int idx = tid; idx < CWARPS * 4 * 256; idx += CTPB) {
        int seg = idx >> 8;                // 0..55
        int off = idx & 255;
        int wp  = seg >> 2;                // dest warp 0..13
        int m   = seg & 3;
        int pp  = wp >> 1, qq = wp & 1;
        int r   = b * RPB + 2 * pp + (m >> 1);
        if (r < NHID) {
            const float* src = ((m & 1) ? Uh : Uz) + (size_t)r * NHID + qq * 1024;
            ((float4*)sU)[wp * 1024 + m * 256 + off] = *(const float4*)(src + off * 4);
        }
    }

    // Owner state: even warps (q==0), lanes 0/1 own rows r0, r0+1.
    int  myrow = r0 + l;
    bool owner = (q == 0) && (l < 2) && (myrow < NHID);
    float z_s = 0.f, ht_s = 0.f, h_s = 0.f, bzr = 0.f;
    if (owner) {
        z_s  = zt0[myrow];
        ht_s = htilde0[myrow];
        h_s  = hprev0[myrow];
        bzr  = bz[myrow];
    }
    // Prologue: store hp_0 = hprev0 and hp_1 = stale combine (both known now).
    if (q == 0) {
        float h1 = (1.0f - z_s) * h_s + z_s * ht_s;   // valid on lanes 0/1
        float h0_l1 = __shfl_sync(0xffffffffu, h_s, 1);
        float h1_l1 = __shfl_sync(0xffffffffu, h1, 1);
        if (l == 0 && r0 < NHID) {
            st_cg2(&g_hp[0][r0], h_s, h0_l1);
            st_cg2(&g_hp[1][r0], h1, h1_l1);
            __threadfence();
        }
        if (owner) h_s = h1;               // h_s tracks hp_{t+1} in the loop
    }
    cbar();
    if (tid == 0) st_flag(&g_flags[b], e0 + 1u);

    const float4* uw = ((const float4*)sU) + (size_t)w * 1024;

    // Iterations t = 0..1022 (last step's dots are dead in the reference).
    for (int t = 0; t < T_STEPS - 1; t++) {
        // Protect reads of hp_t: flag e0+t was posted at end of iter t-2
        // (or prologue for t<2) => poll fast-path in steady state.
        if (tid == 0) poll_ev(e0 + (t < 2 ? 1u : (unsigned)t));
        cbar();                            // bar1: poll visible block-wide

        const float4* hpg = ((const float4*)g_hp[t & 3]) + q * 256;
        float4 hp[8];
#pragma unroll
        for (int j = 0; j < 8; j++)
            hp[j] = __ldcg(hpg + l + 32 * j);

        float xzv = 0.f, xhv = 0.f;
        if (owner) {
            xzv = __ldg(&g_xz[(size_t)t * NHID + myrow]);
            xhv = __ldg(&g_xh[(size_t)t * NHID + myrow]);
        }

        // 4 partial dots over this K-half.
        float d0 = 0.f, d1 = 0.f, d2 = 0.f, d3 = 0.f;
#pragma unroll
        for (int j = 0; j < 8; j++) {
            float4 hv = hp[j];
            float4 a0 = uw[0 * 256 + l + 32 * j];
            d0 = fmaf(a0.x, hv.x, d0); d0 = fmaf(a0.y, hv.y, d0);
            d0 = fmaf(a0.z, hv.z, d0); d0 = fmaf(a0.w, hv.w, d0);
            float4 a1 = uw[1 * 256 + l + 32 * j];
            d1 = fmaf(a1.x, hv.x, d1); d1 = fmaf(a1.y, hv.y, d1);
            d1 = fmaf(a1.z, hv.z, d1); d1 = fmaf(a1.w, hv.w, d1);
            float4 a2 = uw[2 * 256 + l + 32 * j];
            d2 = fmaf(a2.x, hv.x, d2); d2 = fmaf(a2.y, hv.y, d2);
            d2 = fmaf(a2.z, hv.z, d2); d2 = fmaf(a2.w, hv.w, d2);
            float4 a3 = uw[3 * 256 + l + 32 * j];
            d3 = fmaf(a3.x, hv.x, d3); d3 = fmaf(a3.y, hv.y, d3);
            d3 = fmaf(a3.z, hv.z, d3); d3 = fmaf(a3.w, hv.w, d3);
        }
#pragma unroll
        for (int o = 16; o > 0; o >>= 1) {
            d0 += __shfl_xor_sync(0xffffffffu, d0, o);
            d1 += __shfl_xor_sync(0xffffffffu, d1, o);
            d2 += __shfl_xor_sync(0xffffffffu, d2, o);
            d3 += __shfl_xor_sync(0xffffffffu, d3, o);
        }

        if (l == 0) {
            float4 v; v.x = d0; v.y = d1; v.z = d2; v.w = d3;
            *(float4*)&sred4[t & 1][w][0] = v;
        }
        cbar();                            // bar2: partials exchanged

        if (owner) {
            // partial order: [dz(rp0), dh(rp0), dz(rp1), dh(rp1)]
            float dz = sred4[t & 1][2 * p][2 * l + 0] + sred4[t & 1][2 * p + 1][2 * l + 0];
            float dh = sred4[t & 1][2 * p][2 * l + 1] + sred4[t & 1][2 * p + 1][2 * l + 1];
            z_s  = 1.0f / (1.0f + expf(-(xzv + dz + bzr)));
            ht_s = tanhf(xhv + dh);
            // hp_{t+2} = (1-z_t)*hp_{t+1} + z_t*ht_t  (reference order)
            h_s = (1.0f - z_s) * h_s + z_s * ht_s;
        }
        if (q == 0) {
            float hnb = __shfl_sync(0xffffffffu, h_s, 1);
            if (l == 0 && r0 < NHID) {
                st_cg2(&g_hp[(t + 2) & 3][r0], h_s, hnb);
                __threadfence();
            }
        }
        cbar();                            // bar3: hp stores done block-wide
        if (tid == 0) st_flag(&g_flags[b], e0 + (unsigned)t + 2u);
    }

    // hp_{1024} (final h) is in slot 0; covered by flag e0+1024.
    if (tid == 0) poll_ev(e0 + 1024u);
    cbar();

    // logits: warp gw = b*14 + w computes one category.
    {
        int gw = b * CWARPS + w;
        if (gw < NCATS) {
            const float4* wo = (const float4*)(Wout + (size_t)gw * NHID);
            const float4* hf = (const float4*)(g_hp[0]);
            float s = 0.f;
#pragma unroll
            for (int j = 0; j < 16; j++) {
                float4 wv = __ldg(wo + l + 32 * j);
                float4 hv = __ldcg(hf + l + 32 * j);
                s = fmaf(wv.x, hv.x, s); s = fmaf(wv.y, hv.y, s);
                s = fmaf(wv.z, hv.z, s); s = fmaf(wv.w, hv.w, s);
            }
#pragma unroll
            for (int o = 16; o > 0; o >>= 1)
                s += __shfl_xor_sync(0xffffffffu, s, o);
            if (l == 0) {
                g_logits[gw] = s;
                __threadfence();
            }
        }
    }
    cbar();
    if (tid == 0) st_flag(&g_flags[b], e0 + 1025u);

    // softmax over 1000 logits by block 0
    if (b == 0) {
        if (tid == 0) poll_ev(e0 + 1025u);
        cbar();
        float m = -1e30f;
        for (int c = tid; c < NCATS; c += CTPB)
            m = fmaxf(m, __ldcg(&g_logits[c]));
#pragma unroll
        for (int o = 16; o > 0; o >>= 1)
            m = fmaxf(m, __shfl_xor_sync(0xffffffffu, m, o));
        if (l == 0) sredW[w] = m;
        cbar();
        if (tid < 32) {
            float mm = (tid < CWARPS) ? sredW[tid] : -1e30f;
#pragma unroll
            for (int o = 16; o > 0; o >>= 1)
                mm = fmaxf(mm, __shfl_xor_sync(0xffffffffu, mm, o));
            if (tid == 0) sredW[0] = mm;
        }
        cbar();
        float gmax = sredW[0];
        cbar();
        float s = 0.f;
        for (int c = tid; c < NCATS; c += CTPB)
            s += expf(__ldcg(&g_logits[c]) - gmax);
#pragma unroll
        for (int o = 16; o > 0; o >>= 1)
            s += __shfl_xor_sync(0xffffffffu, s, o);
        if (l == 0) sredW[w] = s;
        cbar();
        if (tid < 32) {
            float ss = (tid < CWARPS) ? sredW[tid] : 0.f;
#pragma unroll
            for (int o = 16; o > 0; o >>= 1)
                ss += __shfl_xor_sync(0xffffffffu, ss, o);
            if (tid == 0) sredW[0] = ss;
        }
        cbar();
        float inv = 1.0f / sredW[0];
        for (int c = tid; c < NCATS; c += CTPB)
            out[c] = expf(__ldcg(&g_logits[c]) - gmax) * inv;
    }
}

// ---------------- launch ----------------
extern "C" void kernel_launch(void* const* d_in, const int* in_sizes, int n_in,
                              void* d_out, int out_size) {
    (void)in_sizes; (void)n_in; (void)out_size;
    const float* x    = (const float*)d_in[0];
    const float* Wh   = (const float*)d_in[1];
    const float* Wz   = (const float*)d_in[2];
    // d_in[3] = Wr : dead (rt never used)
    const float* Uh   = (const float*)d_in[4];
    const float* Uz   = (const float*)d_in[5];
    const float* bz   = (const float*)d_in[6];
    // d_in[7] = Ur, d_in[8] = br : dead
    const float* Wout = (const float*)d_in[9];
    // d_in[10] = h0 : dead (overwritten before first use)
    const float* zt0  = (const float*)d_in[11];
    const float* ht0  = (const float*)d_in[12];
    const float* hp0  = (const float*)d_in[13];
    float* out = (float*)d_out;

    const int smem = CWARPS * 4 * 1024 * (int)sizeof(float);  // 229376 B
    cudaFuncSetAttribute(recur_kernel,
                         cudaFuncAttributeMaxDynamicSharedMemorySize, smem);

    dim3 ggrid(NHID / BN, T_STEPS / BM, 2);
    gemm_xw_kernel<<<ggrid, 256>>>(x, Wz, Wh);
    recur_kernel<<<GBLK, RTPB, smem>>>(Uz, Uh, bz, zt0, ht0, hp0, Wout, out);
}